// round 7
// baseline (speedup 1.0000x reference)
#include <cuda_runtime.h>

// TSK fuzzy system, single fused kernel.
// out[n] = sum_r fg_bar[n,r]*(x[n]·W[r]+b[r]);  separable normalization:
// fg_bar[n,r] = prod_m mgn[n,m,digit_m(r)], mgn = mg/sum_j mg.
// out[n] = x[n]·A[n]+c[n], A[n]=sum_r fg_bar W[r], c[n]=sum_r fg_bar b[r].
// f32x2 lanes pack a PAIR OF ADJACENT RULES (W stored once in smem).
// Each lane carries 2 samples (independent accumulator sets for ILP).
// This round: __launch_bounds__(128,6) + interleaved W loads (short live ranges).

#define NSAMP 1024
#define NGROUP 128   // grid.y: rule groups of 512
#define TILES 16     // grid.x: sample tiles of 64

typedef unsigned long long ull;

__device__ float g_part[NGROUP * 9 * NSAMP];  // [g][k][n]
__device__ int g_cnt[TILES];                  // zero-init; reset by finisher

__device__ __forceinline__ ull pack2(float f) {
    ull r; asm("mov.b64 %0, {%1, %1};" : "=l"(r) : "f"(f)); return r;
}
__device__ __forceinline__ ull pack2f(float a, float b) {
    ull r; asm("mov.b64 %0, {%1, %2};" : "=l"(r) : "f"(a), "f"(b)); return r;
}
__device__ __forceinline__ ull mul2(ull a, ull b) {
    ull d; asm("mul.rn.f32x2 %0, %1, %2;" : "=l"(d) : "l"(a), "l"(b)); return d;
}
__device__ __forceinline__ void fma2(ull& d, ull a, ull b) {
    asm("fma.rn.f32x2 %0, %1, %2, %0;" : "+l"(d) : "l"(a), "l"(b));
}
__device__ __forceinline__ void unpack2(ull v, float& lo, float& hi) {
    asm("mov.b64 {%0, %1}, %2;" : "=f"(lo), "=f"(hi) : "l"(v));
}

__global__ __launch_bounds__(128, 6) void tsk_kernel(
    const float* __restrict__ x, const float* __restrict__ center,
    const float* __restrict__ sigma, const float* __restrict__ W,
    const float* __restrict__ b, float* __restrict__ out)
{
    // W pairs: smpair[p*8+k] = {W[2p][k], W[2p+1][k]}, p = 0..255 (512 rules)
    __shared__ __align__(16) ull smpair[2048];   // 16 KB
    __shared__ __align__(16) ull smb[256];       //  2 KB  {b[2p],b[2p+1]}
    __shared__ float s_mg[64 * 33];              // 8.4 KB memberships (padded)
    __shared__ float red[4][64][9];              // 9.2 KB cross-warp reduction
    __shared__ int isLast;

    int tid = threadIdx.x, lane = tid & 31, w = tid >> 5;
    int gy = blockIdx.y, tile = blockIdx.x;

    // ---- stage W (512 rules x 8) as adjacent-rule pairs ----
    const float4* Wg4 = reinterpret_cast<const float4*>(W + (size_t)gy * 4096);
#pragma unroll
    for (int i = tid; i < 512; i += 128) {
        int p = i >> 1, h = i & 1;               // pair p, k-half h
        float4 a = Wg4[(2 * p) * 2 + h];
        float4 c = Wg4[(2 * p + 1) * 2 + h];
        int base = p * 8 + h * 4;
        smpair[base + 0] = pack2f(a.x, c.x);
        smpair[base + 1] = pack2f(a.y, c.y);
        smpair[base + 2] = pack2f(a.z, c.z);
        smpair[base + 3] = pack2f(a.w, c.w);
    }
    {
        const float2* bg = reinterpret_cast<const float2*>(b + gy * 512);
        float2 v = bg[tid * 2], v2 = bg[tid * 2 + 1];
        smb[tid * 2] = pack2f(v.x, v.y);
        smb[tid * 2 + 1] = pack2f(v2.x, v2.y);
    }

    // ---- memberships: 2 threads per sample (4 dims each) ----
    {
        int s = tid & 63, mh = tid >> 6;         // mh: dims 0-3 or 4-7
        int n = tile * 64 + s;
        float4 xv4 = *reinterpret_cast<const float4*>(x + n * 8 + mh * 4);
        float xv[4] = {xv4.x, xv4.y, xv4.z, xv4.w};
#pragma unroll
        for (int mm = 0; mm < 4; mm++) {
            int m = mh * 4 + mm;
            float e[4], sum = 0.f;
#pragma unroll
            for (int j = 0; j < 4; j++) {
                float d = xv[mm] - center[m * 4 + j];
                float sg = sigma[m * 4 + j];
                e[j] = __expf(-0.5f * d * d * sg * sg);
                sum += e[j];
            }
            float inv = 1.0f / sum;
#pragma unroll
            for (int j = 0; j < 4; j++) s_mg[s * 33 + m * 4 + j] = e[j] * inv;
        }
    }
    __syncthreads();

    // ---- per-thread sample pair: n0 = tile*64+lane, n1 = n0+32 ----
    const float* r0 = s_mg + lane * 33;
    const float* r1 = s_mg + (lane + 32) * 33;

    // warp's 128 rules: digits j0..j3 from chunk, j4 in {j4b, j4b+1}
    int chunk = gy * 2 + (w >> 1);
    int d0 = (chunk >> 6) & 3, d1 = (chunk >> 4) & 3, d2 = (chunk >> 2) & 3, d3 = chunk & 3;
    float preA = r0[d0] * r0[4 + d1] * r0[8 + d2] * r0[12 + d3];
    float preB = r1[d0] * r1[4 + d1] * r1[8 + d2] * r1[12 + d3];
    int j4b = (w & 1) * 2;

    float pm4A[2], pm4B[2], pm5A[4], pm5B[4], pm6A[4], pm6B[4];
    ull pm7pA[2], pm7pB[2];
#pragma unroll
    for (int j = 0; j < 2; j++) {
        pm4A[j] = r0[16 + j4b + j];
        pm4B[j] = r1[16 + j4b + j];
    }
#pragma unroll
    for (int j = 0; j < 4; j++) {
        pm5A[j] = r0[20 + j]; pm6A[j] = r0[24 + j];
        pm5B[j] = r1[20 + j]; pm6B[j] = r1[24 + j];
    }
    pm7pA[0] = pack2f(r0[28], r0[29]); pm7pA[1] = pack2f(r0[30], r0[31]);
    pm7pB[0] = pack2f(r1[28], r1[29]); pm7pB[1] = pack2f(r1[30], r1[31]);

    ull aA[9] = {0,0,0,0,0,0,0,0,0};
    ull aB[9] = {0,0,0,0,0,0,0,0,0};

    // ---- main loop: 128 rules/warp as 64 rule-pairs, 2 samples/lane ----
#pragma unroll 1
    for (int j4 = 0; j4 < 2; j4++) {
        float p4A = preA * pm4A[j4];
        float p4B = preB * pm4B[j4];
#pragma unroll 1
        for (int j5 = 0; j5 < 4; j5++) {
            float p5A = p4A * pm5A[j5];
            float p5B = p4B * pm5B[j5];
            int pb = w * 64 + j4 * 32 + j5 * 8;     // pair base (8 pairs here)
            const ulonglong2* wp = reinterpret_cast<const ulonglong2*>(&smpair[pb * 8]);
            const ulonglong2* bq = reinterpret_cast<const ulonglong2*>(&smb[pb]);
#pragma unroll
            for (int j6 = 0; j6 < 4; j6++) {
                ull p6A = pack2(p5A * pm6A[j6]);
                ull p6B = pack2(p5B * pm6B[j6]);
                ull fA0 = mul2(p6A, pm7pA[0]);
                ull fB0 = mul2(p6B, pm7pB[0]);
                const ulonglong2* w0 = wp + j6 * 8;
                // pair 2*j6 (rules j7=0,1): interleaved load/use, short live ranges
                {
                    ulonglong2 q = w0[0];
                    fma2(aA[0], fA0, q.x); fma2(aA[1], fA0, q.y);
                    fma2(aB[0], fB0, q.x); fma2(aB[1], fB0, q.y);
                }
                {
                    ulonglong2 q = w0[1];
                    fma2(aA[2], fA0, q.x); fma2(aA[3], fA0, q.y);
                    fma2(aB[2], fB0, q.x); fma2(aB[3], fB0, q.y);
                }
                {
                    ulonglong2 q = w0[2];
                    fma2(aA[4], fA0, q.x); fma2(aA[5], fA0, q.y);
                    fma2(aB[4], fB0, q.x); fma2(aB[5], fB0, q.y);
                }
                {
                    ulonglong2 q = w0[3];
                    fma2(aA[6], fA0, q.x); fma2(aA[7], fA0, q.y);
                    fma2(aB[6], fB0, q.x); fma2(aB[7], fB0, q.y);
                }
                ull fA1 = mul2(p6A, pm7pA[1]);
                ull fB1 = mul2(p6B, pm7pB[1]);
                // pair 2*j6+1 (rules j7=2,3)
                {
                    ulonglong2 q = w0[4];
                    fma2(aA[0], fA1, q.x); fma2(aA[1], fA1, q.y);
                    fma2(aB[0], fB1, q.x); fma2(aB[1], fB1, q.y);
                }
                {
                    ulonglong2 q = w0[5];
                    fma2(aA[2], fA1, q.x); fma2(aA[3], fA1, q.y);
                    fma2(aB[2], fB1, q.x); fma2(aB[3], fB1, q.y);
                }
                {
                    ulonglong2 q = w0[6];
                    fma2(aA[4], fA1, q.x); fma2(aA[5], fA1, q.y);
                    fma2(aB[4], fB1, q.x); fma2(aB[5], fB1, q.y);
                }
                {
                    ulonglong2 q = w0[7];
                    fma2(aA[6], fA1, q.x); fma2(aA[7], fA1, q.y);
                    fma2(aB[6], fB1, q.x); fma2(aB[7], fB1, q.y);
                }
                {
                    ulonglong2 bb = bq[j6];
                    fma2(aA[8], fA0, bb.x); fma2(aB[8], fB0, bb.x);
                    fma2(aA[8], fA1, bb.y); fma2(aB[8], fB1, bb.y);
                }
            }
        }
    }

    // ---- collapse rule-pair lanes, cross-warp reduction ----
#pragma unroll
    for (int k = 0; k < 9; k++) {
        float lo, hi;
        unpack2(aA[k], lo, hi);
        red[w][lane][k] = lo + hi;
        unpack2(aB[k], lo, hi);
        red[w][lane + 32][k] = lo + hi;
    }
    __syncthreads();

#pragma unroll 1
    for (int idx = tid; idx < 9 * 64; idx += 128) {
        int s = idx & 63;
        int k = idx >> 6;
        float a = red[0][s][k] + red[1][s][k] + red[2][s][k] + red[3][s][k];
        g_part[(gy * 9 + k) * NSAMP + tile * 64 + s] = a;
    }

    // ---- fused finalize: last CTA of this tile reduces over all groups ----
    __threadfence();
    __syncthreads();
    if (tid == 0) {
        int c = atomicAdd(&g_cnt[tile], 1);
        isLast = (c == NGROUP - 1) ? 1 : 0;
    }
    __syncthreads();
    if (isLast) {
        __threadfence();
        float* sA = s_mg;  // reuse: [s][k] 64*9
#pragma unroll 1
        for (int item = tid; item < 9 * 64; item += 128) {
            int k = item >> 6, s = item & 63;
            const float* p = g_part + k * NSAMP + tile * 64 + s;
            float a0 = 0.f, a1 = 0.f, a2 = 0.f, a3 = 0.f;
#pragma unroll 4
            for (int g = 0; g < NGROUP; g += 4) {
                a0 += p[(g + 0) * 9 * NSAMP];
                a1 += p[(g + 1) * 9 * NSAMP];
                a2 += p[(g + 2) * 9 * NSAMP];
                a3 += p[(g + 3) * 9 * NSAMP];
            }
            sA[s * 9 + k] = (a0 + a1) + (a2 + a3);
        }
        __syncthreads();
        if (tid < 64) {
            int n = tile * 64 + tid;
            float o = sA[tid * 9 + 8];
#pragma unroll
            for (int m = 0; m < 8; m++) o = fmaf(x[n * 8 + m], sA[tid * 9 + m], o);
            out[n] = o;
        }
        if (tid == 0) g_cnt[tile] = 0;  // reset for next graph replay
    }
}

extern "C" void kernel_launch(void* const* d_in, const int* in_sizes, int n_in,
                              void* d_out, int out_size) {
    const float* x      = (const float*)d_in[0];
    const float* center = (const float*)d_in[1];
    const float* sigma  = (const float*)d_in[2];
    const float* W      = (const float*)d_in[3];
    const float* b      = (const float*)d_in[4];
    float* out = (float*)d_out;

    dim3 grid(TILES, NGROUP);
    tsk_kernel<<<grid, 128>>>(x, center, sigma, W, b, out);
}